// round 4
// baseline (speedup 1.0000x reference)
#include <cuda_runtime.h>

#define D 64
#define MAXN 100000
#define MAXE 1250000
#define BN_EPS 1e-5f
#define TILE 64

typedef unsigned long long ull;

#define PK2(d, s)  asm("mov.b64 %0, {%1, %1};" : "=l"(d) : "f"(s))
#define FMA2(d, a, b, c) asm("fma.rn.f32x2 %0, %1, %2, %3;" : "=l"(d) : "l"(a), "l"(b), "l"(c))
#define UPK2(lo, hi, s) asm("mov.b64 {%0, %1}, %2;" : "=f"(lo), "=f"(hi) : "l"(s))

// ---------------- static device scratch -------------------------------------
__device__ int   g_deg[MAXN];
__device__ int   g_rowptr[MAXN + 1];
__device__ int   g_cursor[MAXN + 1];
__device__ int   g_blocksums[256];
__device__ int   g_srcsorted[MAXE];
__device__ __align__(16) float g_msg[(size_t)MAXN * D];
__device__ __align__(16) float g_hA[(size_t)MAXN * D];
__device__ __align__(16) float g_hB[(size_t)MAXN * D];
__device__ __align__(16) float g_colsum[D];
__device__ __align__(16) float g_colsq[D];
__device__ __align__(16) float g_scale[D];
__device__ __align__(16) float g_shift[D];

// ---------------- CSR build --------------------------------------------------
__global__ void k_setup(int N) {
    int i = blockIdx.x * blockDim.x + threadIdx.x;
    if (i < N) g_deg[i] = 0;
    if (blockIdx.x == 0 && threadIdx.x < D) {
        g_colsum[threadIdx.x] = 0.f;
        g_colsq[threadIdx.x]  = 0.f;
    }
}

__global__ void k_hist(const int* __restrict__ ei, int E) {
    int e = blockIdx.x * blockDim.x + threadIdx.x;
    if (e < E) atomicAdd(&g_deg[ei[E + e]], 1);
}

__global__ void k_scan1(int N) {
    __shared__ int sh[256];
    int tid = threadIdx.x;
    int base = blockIdx.x * 1024 + tid * 4;
    int v0 = (base + 0 < N) ? g_deg[base + 0] : 0;
    int v1 = (base + 1 < N) ? g_deg[base + 1] : 0;
    int v2 = (base + 2 < N) ? g_deg[base + 2] : 0;
    int v3 = (base + 3 < N) ? g_deg[base + 3] : 0;
    int t0 = v0, t1 = t0 + v1, t2 = t1 + v2, t3 = t2 + v3;
    sh[tid] = t3;
    __syncthreads();
    for (int off = 1; off < 256; off <<= 1) {
        int add = (tid >= off) ? sh[tid - off] : 0;
        __syncthreads();
        sh[tid] += add;
        __syncthreads();
    }
    int excl = sh[tid] - t3;
    if (base + 0 < N) g_rowptr[base + 1] = excl + t0;
    if (base + 1 < N) g_rowptr[base + 2] = excl + t1;
    if (base + 2 < N) g_rowptr[base + 3] = excl + t2;
    if (base + 3 < N) g_rowptr[base + 4] = excl + t3;
    if (tid == 255) g_blocksums[blockIdx.x] = sh[255];
}

__global__ void k_scan2(int NB) {
    __shared__ int sh[256];
    int t = threadIdx.x;
    int v = (t < NB) ? g_blocksums[t] : 0;
    sh[t] = v;
    __syncthreads();
    for (int off = 1; off < 256; off <<= 1) {
        int a = (t >= off) ? sh[t - off] : 0;
        __syncthreads();
        sh[t] += a;
        __syncthreads();
    }
    if (t < NB) g_blocksums[t] = sh[t] - v;   // exclusive
}

__global__ void k_scan3(int N) {
    int base = blockIdx.x * 1024 + threadIdx.x * 4;
    int off = g_blocksums[blockIdx.x];
#pragma unroll
    for (int i = 0; i < 4; i++) {
        int idx = base + i;
        if (idx < N) {
            int v = g_rowptr[idx + 1] + off;
            g_rowptr[idx + 1] = v;
            if (idx + 1 < N) g_cursor[idx + 1] = v;   // cursor[i] = rowptr[i]
        }
    }
    if (blockIdx.x == 0 && threadIdx.x == 0) { g_rowptr[0] = 0; g_cursor[0] = 0; }
}

__global__ void k_bucket(const int* __restrict__ ei, int E) {
    int e = blockIdx.x * blockDim.x + threadIdx.x;
    if (e < E) {
        int d = ei[E + e];
        int pos = atomicAdd(&g_cursor[d], 1);
        g_srcsorted[pos] = ei[e];
    }
}

// ---------------- gather: warp per node, max occupancy ----------------------
__device__ __forceinline__ void bnrelu4(float4& a, const float4& sc, const float4& sh) {
    a.x = fmaxf(fmaf(a.x, sc.x, sh.x), 0.f);
    a.y = fmaxf(fmaf(a.y, sc.y, sh.y), 0.f);
    a.z = fmaxf(fmaf(a.z, sc.z, sh.z), 0.f);
    a.w = fmaxf(fmaf(a.w, sc.w, sh.w), 0.f);
}

template<int TF>
__global__ void __launch_bounds__(256) k_gather(const float* __restrict__ x_src, int N)
{
    int lane = threadIdx.x & 31;
    int node = (blockIdx.x * blockDim.x + threadIdx.x) >> 5;
    if (node >= N) return;
    int half = lane >> 4;
    int c4 = lane & 15;

    float4 sc4, sh4;
    if (TF) { sc4 = ((const float4*)g_scale)[c4]; sh4 = ((const float4*)g_shift)[c4]; }

    float4 mv = make_float4(0.f, 0.f, 0.f, 0.f);
    int rs = g_rowptr[node], re = g_rowptr[node + 1];

    for (int base = rs; base < re; base += 32) {
        int j = base + lane;
        int sj = (j < re) ? g_srcsorted[j] : 0;
        int cnt = min(32, re - base);
        int u = 0;
        for (; u + 8 <= cnt; u += 8) {
            int s0 = __shfl_sync(0xffffffffu, sj, u + half);
            int s1 = __shfl_sync(0xffffffffu, sj, u + 2 + half);
            int s2 = __shfl_sync(0xffffffffu, sj, u + 4 + half);
            int s3 = __shfl_sync(0xffffffffu, sj, u + 6 + half);
            float4 a0 = ((const float4*)(x_src + (size_t)s0 * D))[c4];
            float4 a1 = ((const float4*)(x_src + (size_t)s1 * D))[c4];
            float4 a2 = ((const float4*)(x_src + (size_t)s2 * D))[c4];
            float4 a3 = ((const float4*)(x_src + (size_t)s3 * D))[c4];
            if (TF) { bnrelu4(a0, sc4, sh4); bnrelu4(a1, sc4, sh4); bnrelu4(a2, sc4, sh4); bnrelu4(a3, sc4, sh4); }
            mv.x += (a0.x + a1.x) + (a2.x + a3.x);
            mv.y += (a0.y + a1.y) + (a2.y + a3.y);
            mv.z += (a0.z + a1.z) + (a2.z + a3.z);
            mv.w += (a0.w + a1.w) + (a2.w + a3.w);
        }
        for (; u < cnt; u += 2) {
            int idx = u + half;
            int s = __shfl_sync(0xffffffffu, sj, idx & 31);
            if (idx < cnt) {
                float4 a = ((const float4*)(x_src + (size_t)s * D))[c4];
                if (TF) bnrelu4(a, sc4, sh4);
                mv.x += a.x; mv.y += a.y; mv.z += a.z; mv.w += a.w;
            }
        }
    }

    mv.x += __shfl_xor_sync(0xffffffffu, mv.x, 16);
    mv.y += __shfl_xor_sync(0xffffffffu, mv.y, 16);
    mv.z += __shfl_xor_sync(0xffffffffu, mv.z, 16);
    mv.w += __shfl_xor_sync(0xffffffffu, mv.w, 16);
    if (lane < 16)
        ((float4*)(g_msg + (size_t)node * D))[c4] = mv;
}

// ---------------- block-tiled dual GEMM + BN stats ---------------------------
#define MROW 68
#define OFF_WB  4096
#define OFF_M   8192
#define OFF_X   (8192 + 64 * MROW)
#define OFF_BR  (8192 + 128 * MROW)
#define OFF_SUM (OFF_BR + 64)
#define OFF_SQ  (OFF_SUM + 64)
#define SMEM_FLOATS (OFF_SQ + 64)

template<int TF>
__global__ void __launch_bounds__(256) k_gemm(
    const float* __restrict__ x_src, float* __restrict__ h_out,
    const float* __restrict__ Wrel, const float* __restrict__ brel,
    const float* __restrict__ Wroot, int N)
{
    extern __shared__ float smem[];
    float* wa_sh = smem;
    float* wb_sh = smem + OFF_WB;
    float* m_sh  = smem + OFF_M;
    float* x_sh  = smem + OFF_X;
    float* s_br  = smem + OFF_BR;
    float* s_sum = smem + OFF_SUM;
    float* s_sq  = smem + OFF_SQ;

    int tid = threadIdx.x;
    int lane = tid & 31;
    int tile0 = blockIdx.x * TILE;

    // stage weights
    for (int i = tid; i < 1024; i += 256) {
        ((float4*)wa_sh)[i] = ((const float4*)Wrel)[i];
        ((float4*)wb_sh)[i] = ((const float4*)Wroot)[i];
    }
    if (tid < D) s_br[tid] = brel[tid];
    if (tid >= 64 && tid < 128) { s_sum[tid - 64] = 0.f; s_sq[tid - 64] = 0.f; }

    // stage m and x tiles (uniform coalesced copy; x gets BN+ReLU if TF)
    for (int i = tid; i < 1024; i += 256) {
        int r = i >> 4, c4 = i & 15;
        int node = tile0 + r;
        float4 mval = make_float4(0.f, 0.f, 0.f, 0.f);
        float4 xval = make_float4(0.f, 0.f, 0.f, 0.f);
        if (node < N) {
            mval = ((const float4*)(g_msg + (size_t)node * D))[c4];
            xval = ((const float4*)(x_src + (size_t)node * D))[c4];
            if (TF) {
                float4 sc4 = ((const float4*)g_scale)[c4];
                float4 sh4 = ((const float4*)g_shift)[c4];
                bnrelu4(xval, sc4, sh4);
            }
        }
        ((float4*)(m_sh + r * MROW))[c4] = mval;
        ((float4*)(x_sh + r * MROW))[c4] = xval;
    }
    __syncthreads();

    // block-tiled dual GEMM (FFMA2)
    int r = tid >> 2;
    int cg = tid & 3;
    int c0 = cg * 16;
    int node = tile0 + r;
    bool valid = node < N;

    ull acc[8];
    {
        const ull* br2 = (const ull*)s_br;
#pragma unroll
        for (int q = 0; q < 8; q++) acc[q] = br2[cg * 8 + q];
    }

    const float* mrow = m_sh + r * MROW;
    const float* xrow = x_sh + r * MROW;
#pragma unroll 4
    for (int k = 0; k < D; k++) {
        float mr = mrow[k];
        float xr = xrow[k];
        ull mrr, xrr;
        PK2(mrr, mr);
        PK2(xrr, xr);
        const ulonglong2* wa2 = (const ulonglong2*)(wa_sh + k * D + c0);
        const ulonglong2* wb2 = (const ulonglong2*)(wb_sh + k * D + c0);
        ulonglong2 A0 = wa2[0], A1 = wa2[1], A2 = wa2[2], A3 = wa2[3];
        FMA2(acc[0], mrr, A0.x, acc[0]); FMA2(acc[1], mrr, A0.y, acc[1]);
        FMA2(acc[2], mrr, A1.x, acc[2]); FMA2(acc[3], mrr, A1.y, acc[3]);
        FMA2(acc[4], mrr, A2.x, acc[4]); FMA2(acc[5], mrr, A2.y, acc[5]);
        FMA2(acc[6], mrr, A3.x, acc[6]); FMA2(acc[7], mrr, A3.y, acc[7]);
        ulonglong2 B0 = wb2[0], B1 = wb2[1], B2 = wb2[2], B3 = wb2[3];
        FMA2(acc[0], xrr, B0.x, acc[0]); FMA2(acc[1], xrr, B0.y, acc[1]);
        FMA2(acc[2], xrr, B1.x, acc[2]); FMA2(acc[3], xrr, B1.y, acc[3]);
        FMA2(acc[4], xrr, B2.x, acc[4]); FMA2(acc[5], xrr, B2.y, acc[5]);
        FMA2(acc[6], xrr, B3.x, acc[6]); FMA2(acc[7], xrr, B3.y, acc[7]);
    }

    float h[16];
#pragma unroll
    for (int q = 0; q < 8; q++) UPK2(h[2 * q], h[2 * q + 1], acc[q]);
    if (!valid) {
#pragma unroll
        for (int q = 0; q < 16; q++) h[q] = 0.f;
    }

    // BN stats: reduce over the 8 rows this warp owns (lane bits 2..4)
    float s[16], q2[16];
#pragma unroll
    for (int q = 0; q < 16; q++) { s[q] = h[q]; q2[q] = h[q] * h[q]; }
#pragma unroll
    for (int off = 4; off <= 16; off <<= 1) {
#pragma unroll
        for (int q = 0; q < 16; q++) {
            s[q]  += __shfl_xor_sync(0xffffffffu, s[q], off);
            q2[q] += __shfl_xor_sync(0xffffffffu, q2[q], off);
        }
    }
    if (lane < 4) {
#pragma unroll
        for (int q = 0; q < 16; q++) {
            atomicAdd(&s_sum[lane * 16 + q], s[q]);
            atomicAdd(&s_sq[lane * 16 + q], q2[q]);
        }
    }

    if (valid) {
        float4* out = (float4*)(h_out + (size_t)node * D + c0);
        out[0] = make_float4(h[0], h[1], h[2], h[3]);
        out[1] = make_float4(h[4], h[5], h[6], h[7]);
        out[2] = make_float4(h[8], h[9], h[10], h[11]);
        out[3] = make_float4(h[12], h[13], h[14], h[15]);
    }

    __syncthreads();
    if (tid < 64) atomicAdd(&g_colsum[tid], s_sum[tid]);
    else if (tid < 128) atomicAdd(&g_colsq[tid - 64], s_sq[tid - 64]);
}

__global__ void k_bn(const float* __restrict__ gamma, const float* __restrict__ beta, float invN) {
    int t = threadIdx.x;
    if (t < D) {
        float mean = g_colsum[t] * invN;
        float var  = g_colsq[t] * invN - mean * mean;
        var = var < 0.f ? 0.f : var;
        float sc = gamma[t] * rsqrtf(var + BN_EPS);
        g_scale[t] = sc;
        g_shift[t] = beta[t] - mean * sc;
        g_colsum[t] = 0.f;   // ready for next layer
        g_colsq[t]  = 0.f;
    }
}

// ---------------- pooling + classifier (final BN+ReLU inline) ----------------
__global__ void k_pool(const float* __restrict__ hfin, const int* __restrict__ batch, int N,
                       const float* __restrict__ Wcls, const float* __restrict__ bcls,
                       float* __restrict__ out)
{
    __shared__ float s_pool[D];
    int g = blockIdx.x, tid = threadIdx.x;

    int lo = 0, hi = N;
    while (lo < hi) { int mid = (lo + hi) >> 1; if (batch[mid] < g) lo = mid + 1; else hi = mid; }
    int start = lo;
    hi = N;
    while (lo < hi) { int mid = (lo + hi) >> 1; if (batch[mid] < g + 1) lo = mid + 1; else hi = mid; }
    int end = lo;

    if (tid < D) s_pool[tid] = 0.f;
    __syncthreads();

    int col = tid & 63, rg = tid >> 6;
    float sc = g_scale[col], sh_ = g_shift[col];
    float p = 0.f;
    for (int r = start + rg; r < end; r += 4)
        p += fmaxf(fmaf(hfin[(size_t)r * D + col], sc, sh_), 0.f);
    atomicAdd(&s_pool[col], p);
    __syncthreads();

    float cnt = (float)(end - start);
    float denom = cnt > 1.f ? cnt : 1.f;
    if (tid < D) s_pool[tid] /= denom;
    __syncthreads();

    if (tid < 10) {
        float acc = bcls[tid];
#pragma unroll
        for (int d = 0; d < D; d++) acc = fmaf(s_pool[d], Wcls[d * 10 + tid], acc);
        out[g * 10 + tid] = acc;
    }
}

// ---------------- launch -----------------------------------------------------
extern "C" void kernel_launch(void* const* d_in, const int* in_sizes, int n_in,
                              void* d_out, int out_size)
{
    const float* x     = (const float*)d_in[0];
    const int*   ei    = (const int*)d_in[1];
    const int*   batch = (const int*)d_in[2];
    const float* Wrel  = (const float*)d_in[3];
    const float* brel  = (const float*)d_in[4];
    const float* Wroot = (const float*)d_in[5];
    const float* gamma = (const float*)d_in[6];
    const float* beta  = (const float*)d_in[7];
    const float* Wcls  = (const float*)d_in[8];
    const float* bcls  = (const float*)d_in[9];
    float* out = (float*)d_out;

    int N = in_sizes[0] / D;
    int E = in_sizes[1] / 2;
    int G = out_size / 10;
    int NB = (N + 1023) / 1024;
    float invN = 1.f / (float)N;
    int NTILES = (N + TILE - 1) / TILE;
    int GATHER_BLOCKS = (N * 32 + 255) / 256;
    size_t smemb = SMEM_FLOATS * sizeof(float);

    static int attr_done = 0;
    if (!attr_done) {
        cudaFuncSetAttribute(k_gemm<0>, cudaFuncAttributeMaxDynamicSharedMemorySize, (int)smemb);
        cudaFuncSetAttribute(k_gemm<1>, cudaFuncAttributeMaxDynamicSharedMemorySize, (int)smemb);
        attr_done = 1;
    }

    float *hA, *hB;
    cudaGetSymbolAddress((void**)&hA, g_hA);
    cudaGetSymbolAddress((void**)&hB, g_hB);

    // CSR build (reused by all layers)
    k_setup<<<(N + 255) / 256, 256>>>(N);
    k_hist<<<(E + 255) / 256, 256>>>(ei, E);
    k_scan1<<<NB, 256>>>(N);
    k_scan2<<<1, 256>>>(NB);
    k_scan3<<<NB, 256>>>(N);
    k_bucket<<<(E + 255) / 256, 256>>>(ei, E);

    // layer 0: x -> hA
    k_gather<0><<<GATHER_BLOCKS, 256>>>(x, N);
    k_gemm<0><<<NTILES, 256, smemb>>>(x, hA, Wrel, brel, Wroot, N);
    k_bn<<<1, 64>>>(gamma, beta, invN);

    // layer 1: hA -> hB (BN+ReLU of layer 0 fused into loads)
    k_gather<1><<<GATHER_BLOCKS, 256>>>(hA, N);
    k_gemm<1><<<NTILES, 256, smemb>>>(hA, hB, Wrel + 4096, brel + 64, Wroot + 4096, N);
    k_bn<<<1, 64>>>(gamma + 64, beta + 64, invN);

    // layer 2: hB -> hA
    k_gather<1><<<GATHER_BLOCKS, 256>>>(hB, N);
    k_gemm<1><<<NTILES, 256, smemb>>>(hB, hA, Wrel + 8192, brel + 128, Wroot + 8192, N);
    k_bn<<<1, 64>>>(gamma + 128, beta + 128, invN);

    // pool (applies layer-2 BN+ReLU inline) + classifier
    k_pool<<<G, 256>>>(hA, batch, N, Wcls, bcls, out);
}

// round 5
// speedup vs baseline: 1.9471x; 1.9471x over previous
#include <cuda_runtime.h>

#define D 64
#define MAXN 100000
#define MAXE 1250000
#define BN_EPS 1e-5f
#define TILE 128

typedef unsigned long long ull;

#define PK2(d, s)  asm("mov.b64 %0, {%1, %1};" : "=l"(d) : "f"(s))
#define FMA2(d, a, b, c) asm("fma.rn.f32x2 %0, %1, %2, %3;" : "=l"(d) : "l"(a), "l"(b), "l"(c))
#define UPK2(lo, hi, s) asm("mov.b64 {%0, %1}, %2;" : "=f"(lo), "=f"(hi) : "l"(s))

// ---------------- static device scratch -------------------------------------
__device__ int   g_deg[MAXN];
__device__ int   g_rowptr[MAXN + 1];
__device__ int   g_cursor[MAXN + 1];
__device__ int   g_blocksums[256];
__device__ int   g_srcsorted[MAXE];
__device__ __align__(16) float g_msg[(size_t)MAXN * D];
__device__ __align__(16) float g_hA[(size_t)MAXN * D];
__device__ __align__(16) float g_hB[(size_t)MAXN * D];
__device__ __align__(16) float g_colsum[D];
__device__ __align__(16) float g_colsq[D];
__device__ __align__(16) float g_scale[D];
__device__ __align__(16) float g_shift[D];

// ---------------- CSR build --------------------------------------------------
__global__ void k_setup(int N) {
    int i = blockIdx.x * blockDim.x + threadIdx.x;
    if (i < N) g_deg[i] = 0;
    if (blockIdx.x == 0 && threadIdx.x < D) {
        g_colsum[threadIdx.x] = 0.f;
        g_colsq[threadIdx.x]  = 0.f;
    }
}

__global__ void k_hist(const int* __restrict__ ei, int E) {
    int e = blockIdx.x * blockDim.x + threadIdx.x;
    if (e < E) atomicAdd(&g_deg[ei[E + e]], 1);
}

__global__ void k_scan1(int N) {
    __shared__ int sh[256];
    int tid = threadIdx.x;
    int base = blockIdx.x * 1024 + tid * 4;
    int v0 = (base + 0 < N) ? g_deg[base + 0] : 0;
    int v1 = (base + 1 < N) ? g_deg[base + 1] : 0;
    int v2 = (base + 2 < N) ? g_deg[base + 2] : 0;
    int v3 = (base + 3 < N) ? g_deg[base + 3] : 0;
    int t0 = v0, t1 = t0 + v1, t2 = t1 + v2, t3 = t2 + v3;
    sh[tid] = t3;
    __syncthreads();
    for (int off = 1; off < 256; off <<= 1) {
        int add = (tid >= off) ? sh[tid - off] : 0;
        __syncthreads();
        sh[tid] += add;
        __syncthreads();
    }
    int excl = sh[tid] - t3;
    if (base + 0 < N) g_rowptr[base + 1] = excl + t0;
    if (base + 1 < N) g_rowptr[base + 2] = excl + t1;
    if (base + 2 < N) g_rowptr[base + 3] = excl + t2;
    if (base + 3 < N) g_rowptr[base + 4] = excl + t3;
    if (tid == 255) g_blocksums[blockIdx.x] = sh[255];
}

__global__ void k_scan2(int NB) {
    __shared__ int sh[256];
    int t = threadIdx.x;
    int v = (t < NB) ? g_blocksums[t] : 0;
    sh[t] = v;
    __syncthreads();
    for (int off = 1; off < 256; off <<= 1) {
        int a = (t >= off) ? sh[t - off] : 0;
        __syncthreads();
        sh[t] += a;
        __syncthreads();
    }
    if (t < NB) g_blocksums[t] = sh[t] - v;   // exclusive
}

__global__ void k_scan3(int N) {
    int base = blockIdx.x * 1024 + threadIdx.x * 4;
    int off = g_blocksums[blockIdx.x];
#pragma unroll
    for (int i = 0; i < 4; i++) {
        int idx = base + i;
        if (idx < N) {
            int v = g_rowptr[idx + 1] + off;
            g_rowptr[idx + 1] = v;
            if (idx + 1 < N) g_cursor[idx + 1] = v;
        }
    }
    if (blockIdx.x == 0 && threadIdx.x == 0) { g_rowptr[0] = 0; g_cursor[0] = 0; }
}

__global__ void k_bucket(const int* __restrict__ ei, int E) {
    int e = blockIdx.x * blockDim.x + threadIdx.x;
    if (e < E) {
        int d = ei[E + e];
        int pos = atomicAdd(&g_cursor[d], 1);
        g_srcsorted[pos] = ei[e];
    }
}

// ---------------- gather: warp per node, predicated 8-wide batches ----------
__device__ __forceinline__ void bnrelu4(float4& a, const float4& sc, const float4& sh) {
    a.x = fmaxf(fmaf(a.x, sc.x, sh.x), 0.f);
    a.y = fmaxf(fmaf(a.y, sc.y, sh.y), 0.f);
    a.z = fmaxf(fmaf(a.z, sc.z, sh.z), 0.f);
    a.w = fmaxf(fmaf(a.w, sc.w, sh.w), 0.f);
}

template<int TF>
__global__ void __launch_bounds__(256) k_gather(const float* __restrict__ x_src, int N)
{
    int lane = threadIdx.x & 31;
    int node = (blockIdx.x * blockDim.x + threadIdx.x) >> 5;
    if (node >= N) return;
    int half = lane >> 4;
    int c4 = lane & 15;

    float4 sc4, sh4;
    if (TF) { sc4 = ((const float4*)g_scale)[c4]; sh4 = ((const float4*)g_shift)[c4]; }

    float4 mv = make_float4(0.f, 0.f, 0.f, 0.f);
    int rs = g_rowptr[node], re = g_rowptr[node + 1];

    for (int base = rs; base < re; base += 32) {
        int j = base + lane;
        int sj = (j < re) ? g_srcsorted[j] : 0;
        int cnt = min(32, re - base);
        for (int u = 0; u < cnt; u += 8) {
            int i0 = u + half;
            int s0 = __shfl_sync(0xffffffffu, sj, (i0    ) & 31);
            int s1 = __shfl_sync(0xffffffffu, sj, (i0 + 2) & 31);
            int s2 = __shfl_sync(0xffffffffu, sj, (i0 + 4) & 31);
            int s3 = __shfl_sync(0xffffffffu, sj, (i0 + 6) & 31);
            float4 a0 = make_float4(0.f,0.f,0.f,0.f), a1 = a0, a2 = a0, a3 = a0;
            if (i0     < cnt) { a0 = ((const float4*)(x_src + (size_t)s0 * D))[c4]; if (TF) bnrelu4(a0, sc4, sh4); }
            if (i0 + 2 < cnt) { a1 = ((const float4*)(x_src + (size_t)s1 * D))[c4]; if (TF) bnrelu4(a1, sc4, sh4); }
            if (i0 + 4 < cnt) { a2 = ((const float4*)(x_src + (size_t)s2 * D))[c4]; if (TF) bnrelu4(a2, sc4, sh4); }
            if (i0 + 6 < cnt) { a3 = ((const float4*)(x_src + (size_t)s3 * D))[c4]; if (TF) bnrelu4(a3, sc4, sh4); }
            mv.x += (a0.x + a1.x) + (a2.x + a3.x);
            mv.y += (a0.y + a1.y) + (a2.y + a3.y);
            mv.z += (a0.z + a1.z) + (a2.z + a3.z);
            mv.w += (a0.w + a1.w) + (a2.w + a3.w);
        }
    }

    mv.x += __shfl_xor_sync(0xffffffffu, mv.x, 16);
    mv.y += __shfl_xor_sync(0xffffffffu, mv.y, 16);
    mv.z += __shfl_xor_sync(0xffffffffu, mv.z, 16);
    mv.w += __shfl_xor_sync(0xffffffffu, mv.w, 16);
    if (lane < 16)
        ((float4*)(g_msg + (size_t)node * D))[c4] = mv;
}

// ---------------- block-tiled dual GEMM + BN stats ---------------------------
// 128 nodes/block, 256 threads, 2 nodes/thread, conflict-free padded weights.
#define WROW 68
#define AROW 68
#define OFF_WB  (64 * WROW)                  // 4352
#define OFF_M   (2 * 64 * WROW)              // 8704
#define OFF_X   (OFF_M + TILE * AROW)        // 17408
#define OFF_BR  (OFF_X + TILE * AROW)        // 26112
#define OFF_SUM (OFF_BR + 64)
#define OFF_SQ  (OFF_SUM + 64)
#define SMEM_FLOATS (OFF_SQ + 64)            // 26304 floats = 105216 B

template<int TF>
__global__ void __launch_bounds__(256) k_gemm(
    const float* __restrict__ x_src, float* __restrict__ h_out,
    const float* __restrict__ Wrel, const float* __restrict__ brel,
    const float* __restrict__ Wroot, int N)
{
    extern __shared__ float smem[];
    float* wa_sh = smem;
    float* wb_sh = smem + OFF_WB;
    float* m_sh  = smem + OFF_M;
    float* x_sh  = smem + OFF_X;
    float* s_br  = smem + OFF_BR;
    float* s_sum = smem + OFF_SUM;
    float* s_sq  = smem + OFF_SQ;

    int tid = threadIdx.x;
    int tile0 = blockIdx.x * TILE;

    // stage weights: W[k][c] -> wa_sh[k*68 + c + (c>=32 ? 4 : 0)]
    for (int i = tid; i < 1024; i += 256) {
        int k = i >> 4, cq = i & 15;              // cq = c/4
        int dst = k * 17 + cq + (cq >= 8 ? 1 : 0); // float4 index
        ((float4*)wa_sh)[dst] = ((const float4*)Wrel)[i];
        ((float4*)wb_sh)[dst] = ((const float4*)Wroot)[i];
    }
    if (tid < 64) s_br[tid] = brel[tid];
    if (tid >= 64 && tid < 128) { s_sum[tid - 64] = 0.f; s_sq[tid - 64] = 0.f; }

    // stage m and x tiles
    for (int i = tid; i < TILE * 16; i += 256) {
        int r = i >> 4, c4 = i & 15;
        int node = tile0 + r;
        float4 mval = make_float4(0.f, 0.f, 0.f, 0.f);
        float4 xval = make_float4(0.f, 0.f, 0.f, 0.f);
        if (node < N) {
            mval = ((const float4*)(g_msg + (size_t)node * D))[c4];
            xval = ((const float4*)(x_src + (size_t)node * D))[c4];
            if (TF) {
                float4 sc4 = ((const float4*)g_scale)[c4];
                float4 sh4 = ((const float4*)g_shift)[c4];
                bnrelu4(xval, sc4, sh4);
            }
        }
        ((float4*)(m_sh + r * AROW))[c4] = mval;
        ((float4*)(x_sh + r * AROW))[c4] = xval;
    }
    __syncthreads();

    int lane = tid & 31;
    int cg = lane & 3;
    int p = tid >> 2;          // 0..63 node-pair
    int r0 = p * 2;
    int c0 = cg * 16;                       // logical column base
    int c0f = c0 + (cg >> 1) * 4;           // padded smem offset (banks 0-3,16-19,4-7,20-23)
    int n0 = tile0 + r0, n1 = n0 + 1;

    ull acc0[8], acc1[8];
    {
        const ull* br2 = (const ull*)(s_br + c0);
#pragma unroll
        for (int q = 0; q < 8; q++) { acc0[q] = br2[q]; acc1[q] = br2[q]; }
    }

    const float* m0p = m_sh + r0 * AROW;
    const float* m1p = m_sh + (r0 + 1) * AROW;
    const float* x0p = x_sh + r0 * AROW;
    const float* x1p = x_sh + (r0 + 1) * AROW;

#pragma unroll 2
    for (int k = 0; k < D; k++) {
        ull mm0, mm1, xx0, xx1;
        PK2(mm0, m0p[k]); PK2(mm1, m1p[k]);
        PK2(xx0, x0p[k]); PK2(xx1, x1p[k]);
        const ulonglong2* wa2 = (const ulonglong2*)(wa_sh + k * WROW + c0f);
        const ulonglong2* wb2 = (const ulonglong2*)(wb_sh + k * WROW + c0f);
        ulonglong2 A0 = wa2[0], A1 = wa2[1], A2 = wa2[2], A3 = wa2[3];
        FMA2(acc0[0], mm0, A0.x, acc0[0]); FMA2(acc0[1], mm0, A0.y, acc0[1]);
        FMA2(acc0[2], mm0, A1.x, acc0[2]); FMA2(acc0[3], mm0, A1.y, acc0[3]);
        FMA2(acc0[4], mm0, A2.x, acc0[4]); FMA2(acc0[5], mm0, A2.y, acc0[5]);
        FMA2(acc0[6], mm0, A3.x, acc0[6]); FMA2(acc0[7], mm0, A3.y, acc0[7]);
        FMA2(acc1[0], mm1, A0.x, acc1[0]); FMA2(acc1[1], mm1, A0.y, acc1[1]);
        FMA2(acc1[2], mm1, A1.x, acc1[2]); FMA2(acc1[3], mm1, A1.y, acc1[3]);
        FMA2(acc1[4], mm1, A2.x, acc1[4]); FMA2(acc1[5], mm1, A2.y, acc1[5]);
        FMA2(acc1[6], mm1, A3.x, acc1[6]); FMA2(acc1[7], mm1, A3.y, acc1[7]);
        ulonglong2 B0 = wb2[0], B1 = wb2[1], B2 = wb2[2], B3 = wb2[3];
        FMA2(acc0[0], xx0, B0.x, acc0[0]); FMA2(acc0[1], xx0, B0.y, acc0[1]);
        FMA2(acc0[2], xx0, B1.x, acc0[2]); FMA2(acc0[3], xx0, B1.y, acc0[3]);
        FMA2(acc0[4], xx0, B2.x, acc0[4]); FMA2(acc0[5], xx0, B2.y, acc0[5]);
        FMA2(acc0[6], xx0, B3.x, acc0[6]); FMA2(acc0[7], xx0, B3.y, acc0[7]);
        FMA2(acc1[0], xx1, B0.x, acc1[0]); FMA2(acc1[1], xx1, B0.y, acc1[1]);
        FMA2(acc1[2], xx1, B1.x, acc1[2]); FMA2(acc1[3], xx1, B1.y, acc1[3]);
        FMA2(acc1[4], xx1, B2.x, acc1[4]); FMA2(acc1[5], xx1, B2.y, acc1[5]);
        FMA2(acc1[6], xx1, B3.x, acc1[6]); FMA2(acc1[7], xx1, B3.y, acc1[7]);
    }

    float h0[16], h1[16];
#pragma unroll
    for (int q = 0; q < 8; q++) {
        UPK2(h0[2 * q], h0[2 * q + 1], acc0[q]);
        UPK2(h1[2 * q], h1[2 * q + 1], acc1[q]);
    }
    bool v0 = n0 < N, v1 = n1 < N;
    if (!v0) {
#pragma unroll
        for (int q = 0; q < 16; q++) h0[q] = 0.f;
    }
    if (!v1) {
#pragma unroll
        for (int q = 0; q < 16; q++) h1[q] = 0.f;
    }

    // BN stats: combine 2 nodes, reduce over the 8 p-groups in the warp
    float s[16], q2[16];
#pragma unroll
    for (int q = 0; q < 16; q++) {
        float a = h0[q], b = h1[q];
        s[q] = a + b;
        q2[q] = a * a + b * b;
    }
#pragma unroll
    for (int off = 4; off <= 16; off <<= 1) {
#pragma unroll
        for (int q = 0; q < 16; q++) {
            s[q]  += __shfl_xor_sync(0xffffffffu, s[q], off);
            q2[q] += __shfl_xor_sync(0xffffffffu, q2[q], off);
        }
    }
    if (lane < 4) {
#pragma unroll
        for (int q = 0; q < 16; q++) {
            atomicAdd(&s_sum[c0 + q], s[q]);
            atomicAdd(&s_sq[c0 + q], q2[q]);
        }
    }

    if (v0) {
        float4* o = (float4*)(h_out + (size_t)n0 * D + c0);
        o[0] = make_float4(h0[0], h0[1], h0[2], h0[3]);
        o[1] = make_float4(h0[4], h0[5], h0[6], h0[7]);
        o[2] = make_float4(h0[8], h0[9], h0[10], h0[11]);
        o[3] = make_float4(h0[12], h0[13], h0[14], h0[15]);
    }
    if (v1) {
        float4* o = (float4*)(h_out + (size_t)n1 * D + c0);
        o[0] = make_float4(h1[0], h1[1], h1[2], h1[3]);
        o[1] = make_float4(h1[4], h1[5], h1[6], h1[7]);
        o[2] = make_float4(h1[8], h1[9], h1[10], h1[11]);
        o[3] = make_float4(h1[12], h1[13], h1[14], h1[15]);
    }

    __syncthreads();
    if (tid < 64) atomicAdd(&g_colsum[tid], s_sum[tid]);
    else if (tid < 128) atomicAdd(&g_colsq[tid - 64], s_sq[tid - 64]);
}

__global__ void k_bn(const float* __restrict__ gamma, const float* __restrict__ beta, float invN) {
    int t = threadIdx.x;
    if (t < D) {
        float mean = g_colsum[t] * invN;
        float var  = g_colsq[t] * invN - mean * mean;
        var = var < 0.f ? 0.f : var;
        float sc = gamma[t] * rsqrtf(var + BN_EPS);
        g_scale[t] = sc;
        g_shift[t] = beta[t] - mean * sc;
        g_colsum[t] = 0.f;
        g_colsq[t]  = 0.f;
    }
}

// ---------------- pooling + classifier (final BN+ReLU inline, MLP=4) --------
__global__ void k_pool(const float* __restrict__ hfin, const int* __restrict__ batch, int N,
                       const float* __restrict__ Wcls, const float* __restrict__ bcls,
                       float* __restrict__ out)
{
    __shared__ float s_pool[D];
    int g = blockIdx.x, tid = threadIdx.x;

    int lo = 0, hi = N;
    while (lo < hi) { int mid = (lo + hi) >> 1; if (batch[mid] < g) lo = mid + 1; else hi = mid; }
    int start = lo;
    hi = N;
    while (lo < hi) { int mid = (lo + hi) >> 1; if (batch[mid] < g + 1) lo = mid + 1; else hi = mid; }
    int end = lo;

    if (tid < D) s_pool[tid] = 0.f;
    __syncthreads();

    int col = tid & 63, rg = tid >> 6;
    float sc = g_scale[col], sh_ = g_shift[col];
    float p0 = 0.f, p1 = 0.f, p2 = 0.f, p3 = 0.f;
    int r = start + rg;
    for (; r + 12 < end; r += 16) {
        float a0 = hfin[(size_t)(r     ) * D + col];
        float a1 = hfin[(size_t)(r +  4) * D + col];
        float a2 = hfin[(size_t)(r +  8) * D + col];
        float a3 = hfin[(size_t)(r + 12) * D + col];
        p0 += fmaxf(fmaf(a0, sc, sh_), 0.f);
        p1 += fmaxf(fmaf(a1, sc, sh_), 0.f);
        p2 += fmaxf(fmaf(a2, sc, sh_), 0.f);
        p3 += fmaxf(fmaf(a3, sc, sh_), 0.f);
    }
    for (; r < end; r += 4)
        p0 += fmaxf(fmaf(hfin[(size_t)r * D + col], sc, sh_), 0.f);
    atomicAdd(&s_pool[col], ((p0 + p1) + (p2 + p3)));
    __syncthreads();

    float cnt = (float)(end - start);
    float denom = cnt > 1.f ? cnt : 1.f;
    if (tid < D) s_pool[tid] /= denom;
    __syncthreads();

    if (tid < 10) {
        float acc = bcls[tid];
#pragma unroll
        for (int d = 0; d < D; d++) acc = fmaf(s_pool[d], Wcls[d * 10 + tid], acc);
        out[g * 10 + tid] = acc;
    }
}

// ---------------- launch -----------------------------------------------------
extern "C" void kernel_launch(void* const* d_in, const int* in_sizes, int n_in,
                              void* d_out, int out_size)
{
    const float* x     = (const float*)d_in[0];
    const int*   ei    = (const int*)d_in[1];
    const int*   batch = (const int*)d_in[2];
    const float* Wrel  = (const float*)d_in[3];
    const float* brel  = (const float*)d_in[4];
    const float* Wroot = (const float*)d_in[5];
    const float* gamma = (const float*)d_in[6];
    const float* beta  = (const float*)d_in[7];
    const float* Wcls  = (const float*)d_in[8];
    const float* bcls  = (const float*)d_in[9];
    float* out = (float*)d_out;

    int N = in_sizes[0] / D;
    int E = in_sizes[1] / 2;
    int G = out_size / 10;
    int NB = (N + 1023) / 1024;
    float invN = 1.f / (float)N;
    int NTILES = (N + TILE - 1) / TILE;
    int GATHER_BLOCKS = (N * 32 + 255) / 256;
    size_t smemb = SMEM_FLOATS * sizeof(float);

    static int attr_done = 0;
    if (!attr_done) {
        cudaFuncSetAttribute(k_gemm<0>, cudaFuncAttributeMaxDynamicSharedMemorySize, (int)smemb);
        cudaFuncSetAttribute(k_gemm<1>, cudaFuncAttributeMaxDynamicSharedMemorySize, (int)smemb);
        attr_done = 1;
    }

    float *hA, *hB;
    cudaGetSymbolAddress((void**)&hA, g_hA);
    cudaGetSymbolAddress((void**)&hB, g_hB);

    // CSR build (reused by all layers)
    k_setup<<<(N + 255) / 256, 256>>>(N);
    k_hist<<<(E + 255) / 256, 256>>>(ei, E);
    k_scan1<<<NB, 256>>>(N);
    k_scan2<<<1, 256>>>(NB);
    k_scan3<<<NB, 256>>>(N);
    k_bucket<<<(E + 255) / 256, 256>>>(ei, E);

    // layer 0: x -> hA
    k_gather<0><<<GATHER_BLOCKS, 256>>>(x, N);
    k_gemm<0><<<NTILES, 256, smemb>>>(x, hA, Wrel, brel, Wroot, N);
    k_bn<<<1, 64>>>(gamma, beta, invN);

    // layer 1: hA -> hB (BN+ReLU of layer 0 fused into loads)
    k_gather<1><<<GATHER_BLOCKS, 256>>>(hA, N);
    k_gemm<1><<<NTILES, 256, smemb>>>(hA, hB, Wrel + 4096, brel + 64, Wroot + 4096, N);
    k_bn<<<1, 64>>>(gamma + 64, beta + 64, invN);

    // layer 2: hB -> hA
    k_gather<1><<<GATHER_BLOCKS, 256>>>(hB, N);
    k_gemm<1><<<NTILES, 256, smemb>>>(hB, hA, Wrel + 8192, brel + 128, Wroot + 8192, N);
    k_bn<<<1, 64>>>(gamma + 128, beta + 128, invN);

    // pool (applies layer-2 BN+ReLU inline) + classifier
    k_pool<<<G, 256>>>(hA, batch, N, Wcls, bcls, out);
}

// round 6
// speedup vs baseline: 2.1981x; 1.1289x over previous
#include <cuda_runtime.h>

#define D 64
#define MAXN 100000
#define MAXE 1250000
#define BN_EPS 1e-5f
#define TILE 128

typedef unsigned long long ull;

#define PK2(d, s)  asm("mov.b64 %0, {%1, %1};" : "=l"(d) : "f"(s))
#define FMA2(d, a, b, c) asm("fma.rn.f32x2 %0, %1, %2, %3;" : "=l"(d) : "l"(a), "l"(b), "l"(c))
#define UPK2(lo, hi, s) asm("mov.b64 {%0, %1}, %2;" : "=f"(lo), "=f"(hi) : "l"(s))

// ---------------- static device scratch -------------------------------------
__device__ int   g_deg[MAXN];
__device__ int   g_rowptr[MAXN + 1];
__device__ int   g_cursor[MAXN + 1];
__device__ int   g_blocksums[256];
__device__ int   g_srcsorted[MAXE];
__device__ __align__(16) float g_msg[(size_t)MAXN * D];
__device__ __align__(16) float g_hA[(size_t)MAXN * D];
__device__ __align__(16) float g_hB[(size_t)MAXN * D];
__device__ __align__(16) float g_ssum0[D];
__device__ __align__(16) float g_ssq0[D];
__device__ __align__(16) float g_ssum1[D];
__device__ __align__(16) float g_ssq1[D];

// ---------------- CSR build --------------------------------------------------
__global__ void k_setup(int N) {
    int i = blockIdx.x * blockDim.x + threadIdx.x;
    if (i < N) g_deg[i] = 0;
    if (blockIdx.x == 0 && threadIdx.x < D) {
        g_ssum0[threadIdx.x] = 0.f; g_ssq0[threadIdx.x] = 0.f;
        g_ssum1[threadIdx.x] = 0.f; g_ssq1[threadIdx.x] = 0.f;
    }
}

__global__ void k_hist(const int* __restrict__ ei, int E) {
    int e = blockIdx.x * blockDim.x + threadIdx.x;
    if (e < E) atomicAdd(&g_deg[ei[E + e]], 1);
}

__global__ void k_scan1(int N) {
    __shared__ int sh[256];
    int tid = threadIdx.x;
    int base = blockIdx.x * 1024 + tid * 4;
    int v0 = (base + 0 < N) ? g_deg[base + 0] : 0;
    int v1 = (base + 1 < N) ? g_deg[base + 1] : 0;
    int v2 = (base + 2 < N) ? g_deg[base + 2] : 0;
    int v3 = (base + 3 < N) ? g_deg[base + 3] : 0;
    int t0 = v0, t1 = t0 + v1, t2 = t1 + v2, t3 = t2 + v3;
    sh[tid] = t3;
    __syncthreads();
    for (int off = 1; off < 256; off <<= 1) {
        int add = (tid >= off) ? sh[tid - off] : 0;
        __syncthreads();
        sh[tid] += add;
        __syncthreads();
    }
    int excl = sh[tid] - t3;
    if (base + 0 < N) g_rowptr[base + 1] = excl + t0;
    if (base + 1 < N) g_rowptr[base + 2] = excl + t1;
    if (base + 2 < N) g_rowptr[base + 3] = excl + t2;
    if (base + 3 < N) g_rowptr[base + 4] = excl + t3;
    if (tid == 255) g_blocksums[blockIdx.x] = sh[255];
}

// fused: every block re-scans blocksums, then applies its offset + fills cursor
__global__ void k_scan23(int N, int NB) {
    __shared__ int sh[256];
    int tid = threadIdx.x;
    int v = (tid < NB) ? g_blocksums[tid] : 0;
    sh[tid] = v;
    __syncthreads();
    for (int off = 1; off < 256; off <<= 1) {
        int a = (tid >= off) ? sh[tid - off] : 0;
        __syncthreads();
        sh[tid] += a;
        __syncthreads();
    }
    int off = (blockIdx.x == 0) ? 0 : sh[blockIdx.x - 1];

    int base = blockIdx.x * 1024 + tid * 4;
#pragma unroll
    for (int i = 0; i < 4; i++) {
        int idx = base + i;
        if (idx < N) {
            int val = g_rowptr[idx + 1] + off;
            g_rowptr[idx + 1] = val;
            if (idx + 1 < N) g_cursor[idx + 1] = val;
        }
    }
    if (blockIdx.x == 0 && tid == 0) { g_rowptr[0] = 0; g_cursor[0] = 0; }
}

__global__ void k_bucket(const int* __restrict__ ei, int E) {
    int e = blockIdx.x * blockDim.x + threadIdx.x;
    if (e < E) {
        int d = ei[E + e];
        int pos = atomicAdd(&g_cursor[d], 1);
        g_srcsorted[pos] = ei[e];
    }
}

// ---------------- gather: warp per node, predicated 8-wide batches ----------
__device__ __forceinline__ void bnrelu4(float4& a, const float4& sc, const float4& sh) {
    a.x = fmaxf(fmaf(a.x, sc.x, sh.x), 0.f);
    a.y = fmaxf(fmaf(a.y, sc.y, sh.y), 0.f);
    a.z = fmaxf(fmaf(a.z, sc.z, sh.z), 0.f);
    a.w = fmaxf(fmaf(a.w, sc.w, sh.w), 0.f);
}

template<int TF>
__global__ void __launch_bounds__(256) k_gather(
    const float* __restrict__ x_src,
    const float* __restrict__ ssum, const float* __restrict__ ssq,
    const float* __restrict__ gamma_p, const float* __restrict__ beta_p,
    float* zsum, float* zsq, float invN, int N)
{
    // zero next layer's stats buffer (single block; no one reads it this kernel)
    if (TF && zsum != nullptr && blockIdx.x == 0 && threadIdx.x < D) {
        zsum[threadIdx.x] = 0.f;
        zsq[threadIdx.x]  = 0.f;
    }

    int lane = threadIdx.x & 31;
    int node = (blockIdx.x * blockDim.x + threadIdx.x) >> 5;
    if (node >= N) return;
    int half = lane >> 4;
    int c4 = lane & 15;

    float4 sc4, sh4;
    if (TF) {
#pragma unroll
        for (int c = 0; c < 4; c++) {
            int col = c4 * 4 + c;
            float mean = ssum[col] * invN;
            float var = fmaf(-mean, mean, ssq[col] * invN);
            var = var < 0.f ? 0.f : var;
            float s = gamma_p[col] * rsqrtf(var + BN_EPS);
            ((float*)&sc4)[c] = s;
            ((float*)&sh4)[c] = beta_p[col] - mean * s;
        }
    }

    float4 mv = make_float4(0.f, 0.f, 0.f, 0.f);
    int rs = g_rowptr[node], re = g_rowptr[node + 1];

    for (int base = rs; base < re; base += 32) {
        int j = base + lane;
        int sj = (j < re) ? g_srcsorted[j] : 0;
        int cnt = min(32, re - base);
        for (int u = 0; u < cnt; u += 8) {
            int i0 = u + half;
            int s0 = __shfl_sync(0xffffffffu, sj, (i0    ) & 31);
            int s1 = __shfl_sync(0xffffffffu, sj, (i0 + 2) & 31);
            int s2 = __shfl_sync(0xffffffffu, sj, (i0 + 4) & 31);
            int s3 = __shfl_sync(0xffffffffu, sj, (i0 + 6) & 31);
            float4 a0 = make_float4(0.f,0.f,0.f,0.f), a1 = a0, a2 = a0, a3 = a0;
            if (i0     < cnt) { a0 = ((const float4*)(x_src + (size_t)s0 * D))[c4]; if (TF) bnrelu4(a0, sc4, sh4); }
            if (i0 + 2 < cnt) { a1 = ((const float4*)(x_src + (size_t)s1 * D))[c4]; if (TF) bnrelu4(a1, sc4, sh4); }
            if (i0 + 4 < cnt) { a2 = ((const float4*)(x_src + (size_t)s2 * D))[c4]; if (TF) bnrelu4(a2, sc4, sh4); }
            if (i0 + 6 < cnt) { a3 = ((const float4*)(x_src + (size_t)s3 * D))[c4]; if (TF) bnrelu4(a3, sc4, sh4); }
            mv.x += (a0.x + a1.x) + (a2.x + a3.x);
            mv.y += (a0.y + a1.y) + (a2.y + a3.y);
            mv.z += (a0.z + a1.z) + (a2.z + a3.z);
            mv.w += (a0.w + a1.w) + (a2.w + a3.w);
        }
    }

    mv.x += __shfl_xor_sync(0xffffffffu, mv.x, 16);
    mv.y += __shfl_xor_sync(0xffffffffu, mv.y, 16);
    mv.z += __shfl_xor_sync(0xffffffffu, mv.z, 16);
    mv.w += __shfl_xor_sync(0xffffffffu, mv.w, 16);
    if (lane < 16)
        ((float4*)(g_msg + (size_t)node * D))[c4] = mv;
}

// ---------------- block-tiled dual GEMM + BN stats ---------------------------
// 128 nodes/block, 128 threads, 4 nodes/thread, conflict-free padded weights.
#define WROW 68
#define AROW 68
#define OFF_WB  (64 * WROW)                  // 4352
#define OFF_M   (2 * 64 * WROW)              // 8704
#define OFF_X   (OFF_M + TILE * AROW)        // 17408
#define OFF_BR  (OFF_X + TILE * AROW)        // 26112
#define OFF_SC  (OFF_BR + 64)
#define OFF_SH  (OFF_SC + 64)
#define OFF_SUM (OFF_SH + 64)
#define OFF_SQ  (OFF_SUM + 64)
#define SMEM_FLOATS (OFF_SQ + 64)            // 26432 floats = 105728 B

template<int TF>
__global__ void __launch_bounds__(128) k_gemm(
    const float* __restrict__ x_src, float* __restrict__ h_out,
    const float* __restrict__ Wrel, const float* __restrict__ brel,
    const float* __restrict__ Wroot,
    const float* __restrict__ ssum_in, const float* __restrict__ ssq_in,
    const float* __restrict__ gamma_p, const float* __restrict__ beta_p,
    float* __restrict__ ssum_out, float* __restrict__ ssq_out,
    float invN, int N)
{
    extern __shared__ float smem[];
    float* wa_sh = smem;
    float* wb_sh = smem + OFF_WB;
    float* m_sh  = smem + OFF_M;
    float* x_sh  = smem + OFF_X;
    float* s_br  = smem + OFF_BR;
    float* s_sc  = smem + OFF_SC;
    float* s_shf = smem + OFF_SH;
    float* s_sum = smem + OFF_SUM;
    float* s_sq  = smem + OFF_SQ;

    int tid = threadIdx.x;
    int tile0 = blockIdx.x * TILE;

    // stage weights: W[k][c] -> wa_sh[k*68 + c + (c>=32 ? 4 : 0)]
    for (int i = tid; i < 1024; i += 128) {
        int k = i >> 4, cq = i & 15;
        int dst = k * 17 + cq + (cq >= 8 ? 1 : 0);
        ((float4*)wa_sh)[dst] = ((const float4*)Wrel)[i];
        ((float4*)wb_sh)[dst] = ((const float4*)Wroot)[i];
    }
    if (tid < 64) {
        s_br[tid] = brel[tid];
        s_sum[tid] = 0.f;
        if (TF) {
            float mean = ssum_in[tid] * invN;
            float var = fmaf(-mean, mean, ssq_in[tid] * invN);
            var = var < 0.f ? 0.f : var;
            float s = gamma_p[tid] * rsqrtf(var + BN_EPS);
            s_sc[tid] = s;
            s_shf[tid] = beta_p[tid] - mean * s;
        }
    } else {
        s_sq[tid - 64] = 0.f;
    }
    __syncthreads();

    // stage m and x tiles (x gets BN+ReLU if TF)
    for (int i = tid; i < TILE * 16; i += 128) {
        int r = i >> 4, c4 = i & 15;
        int node = tile0 + r;
        float4 mval = make_float4(0.f, 0.f, 0.f, 0.f);
        float4 xval = make_float4(0.f, 0.f, 0.f, 0.f);
        if (node < N) {
            mval = ((const float4*)(g_msg + (size_t)node * D))[c4];
            xval = ((const float4*)(x_src + (size_t)node * D))[c4];
            if (TF) {
                float4 sc4 = ((const float4*)s_sc)[c4];
                float4 sh4 = ((const float4*)s_shf)[c4];
                bnrelu4(xval, sc4, sh4);
            }
        }
        ((float4*)(m_sh + r * AROW))[c4] = mval;
        ((float4*)(x_sh + r * AROW))[c4] = xval;
    }
    __syncthreads();

    int lane = tid & 31;
    int cg = tid & 3;
    int p = tid >> 2;               // node quad 0..31
    int r0 = p * 4;
    int c0 = cg * 16;
    int c0f = c0 + (cg >> 1) * 4;   // padded offset: banks {0-3,16-19,4-7,20-23}

    ull acc[4][8];
    {
        const ull* br2 = (const ull*)(s_br + c0);
#pragma unroll
        for (int q = 0; q < 8; q++) {
            ull b = br2[q];
            acc[0][q] = b; acc[1][q] = b; acc[2][q] = b; acc[3][q] = b;
        }
    }

#pragma unroll 2
    for (int kk = 0; kk < 16; kk++) {
        float4 mq[4], xq[4];
#pragma unroll
        for (int j = 0; j < 4; j++) {
            mq[j] = *(const float4*)(m_sh + (r0 + j) * AROW + kk * 4);
            xq[j] = *(const float4*)(x_sh + (r0 + j) * AROW + kk * 4);
        }
#pragma unroll
        for (int dk = 0; dk < 4; dk++) {
            int k = kk * 4 + dk;
            const ulonglong2* wa2 = (const ulonglong2*)(wa_sh + k * WROW + c0f);
            const ulonglong2* wb2 = (const ulonglong2*)(wb_sh + k * WROW + c0f);
            ulonglong2 A0 = wa2[0], A1 = wa2[1], A2 = wa2[2], A3 = wa2[3];
            ulonglong2 B0 = wb2[0], B1 = wb2[1], B2 = wb2[2], B3 = wb2[3];
#pragma unroll
            for (int j = 0; j < 4; j++) {
                ull mm, xx;
                PK2(mm, ((const float*)&mq[j])[dk]);
                PK2(xx, ((const float*)&xq[j])[dk]);
                FMA2(acc[j][0], mm, A0.x, acc[j][0]); FMA2(acc[j][1], mm, A0.y, acc[j][1]);
                FMA2(acc[j][2], mm, A1.x, acc[j][2]); FMA2(acc[j][3], mm, A1.y, acc[j][3]);
                FMA2(acc[j][4], mm, A2.x, acc[j][4]); FMA2(acc[j][5], mm, A2.y, acc[j][5]);
                FMA2(acc[j][6], mm, A3.x, acc[j][6]); FMA2(acc[j][7], mm, A3.y, acc[j][7]);
                FMA2(acc[j][0], xx, B0.x, acc[j][0]); FMA2(acc[j][1], xx, B0.y, acc[j][1]);
                FMA2(acc[j][2], xx, B1.x, acc[j][2]); FMA2(acc[j][3], xx, B1.y, acc[j][3]);
                FMA2(acc[j][4], xx, B2.x, acc[j][4]); FMA2(acc[j][5], xx, B2.y, acc[j][5]);
                FMA2(acc[j][6], xx, B3.x, acc[j][6]); FMA2(acc[j][7], xx, B3.y, acc[j][7]);
            }
        }
    }

    // unpack, mask invalid, stats + store
    float s[16], q2[16];
#pragma unroll
    for (int q = 0; q < 16; q++) { s[q] = 0.f; q2[q] = 0.f; }

#pragma unroll
    for (int j = 0; j < 4; j++) {
        int node = tile0 + r0 + j;
        bool valid = node < N;
        float h[16];
#pragma unroll
        for (int q = 0; q < 8; q++) UPK2(h[2 * q], h[2 * q + 1], acc[j][q]);
        if (!valid) {
#pragma unroll
            for (int q = 0; q < 16; q++) h[q] = 0.f;
        }
#pragma unroll
        for (int q = 0; q < 16; q++) { s[q] += h[q]; q2[q] = fmaf(h[q], h[q], q2[q]); }
        if (valid) {
            float4* o = (float4*)(h_out + (size_t)node * D + c0);
            o[0] = make_float4(h[0], h[1], h[2], h[3]);
            o[1] = make_float4(h[4], h[5], h[6], h[7]);
            o[2] = make_float4(h[8], h[9], h[10], h[11]);
            o[3] = make_float4(h[12], h[13], h[14], h[15]);
        }
    }

#pragma unroll
    for (int off = 4; off <= 16; off <<= 1) {
#pragma unroll
        for (int q = 0; q < 16; q++) {
            s[q]  += __shfl_xor_sync(0xffffffffu, s[q], off);
            q2[q] += __shfl_xor_sync(0xffffffffu, q2[q], off);
        }
    }
    if (lane < 4) {
        int cc = lane * 16;
#pragma unroll
        for (int q = 0; q < 16; q++) {
            atomicAdd(&s_sum[cc + q], s[q]);
            atomicAdd(&s_sq[cc + q], q2[q]);
        }
    }

    __syncthreads();
    if (tid < 64) atomicAdd(&ssum_out[tid], s_sum[tid]);
    else atomicAdd(&ssq_out[tid - 64], s_sq[tid - 64]);
}

// ---------------- pooling + classifier (final BN+ReLU inline, MLP=4) --------
__global__ void k_pool(const float* __restrict__ hfin, const int* __restrict__ batch, int N,
                       const float* __restrict__ Wcls, const float* __restrict__ bcls,
                       const float* __restrict__ ssum, const float* __restrict__ ssq,
                       const float* __restrict__ gamma_p, const float* __restrict__ beta_p,
                       float invN, float* __restrict__ out)
{
    __shared__ float s_pool[D];
    int g = blockIdx.x, tid = threadIdx.x;

    int lo = 0, hi = N;
    while (lo < hi) { int mid = (lo + hi) >> 1; if (batch[mid] < g) lo = mid + 1; else hi = mid; }
    int start = lo;
    hi = N;
    while (lo < hi) { int mid = (lo + hi) >> 1; if (batch[mid] < g + 1) lo = mid + 1; else hi = mid; }
    int end = lo;

    if (tid < D) s_pool[tid] = 0.f;
    __syncthreads();

    int col = tid & 63, rg = tid >> 6;
    float mean = ssum[col] * invN;
    float var = fmaf(-mean, mean, ssq[col] * invN);
    var = var < 0.f ? 0.f : var;
    float sc = gamma_p[col] * rsqrtf(var + BN_EPS);
    float sh_ = beta_p[col] - mean * sc;

    float p0 = 0.f, p1 = 0.f, p2 = 0.f, p3 = 0.f;
    int r = start + rg;
    for (; r + 12 < end; r += 16) {
        float a0 = hfin[(size_t)(r     ) * D + col];
        float a1 = hfin[(size_t)(r +  4) * D + col];
        float a2 = hfin[(size_t)(r +  8) * D + col];
        float a3 = hfin[(size_t)(r + 12) * D + col];
        p0 += fmaxf(fmaf(a0, sc, sh_), 0.f);
        p1 += fmaxf(fmaf(a1, sc, sh_), 0.f);
        p2 += fmaxf(fmaf(a2, sc, sh_), 0.f);
        p3 += fmaxf(fmaf(a3, sc, sh_), 0.f);
    }
    for (; r < end; r += 4)
        p0 += fmaxf(fmaf(hfin[(size_t)r * D + col], sc, sh_), 0.f);
    atomicAdd(&s_pool[col], ((p0 + p1) + (p2 + p3)));
    __syncthreads();

    float cnt = (float)(end - start);
    float denom = cnt > 1.f ? cnt : 1.f;
    if (tid < D) s_pool[tid] /= denom;
    __syncthreads();

    if (tid < 10) {
        float acc = bcls[tid];
#pragma unroll
        for (int d = 0; d < D; d++) acc = fmaf(s_pool[d], Wcls[d * 10 + tid], acc);
        out[g * 10 + tid] = acc;
    }
}

// ---------------- launch -----------------------------------------------------
extern "C" void kernel_launch(void* const* d_in, const int* in_sizes, int n_in,
                              void* d_out, int out_size)
{
    const float* x     = (const float*)d_in[0];
    const int*   ei    = (const int*)d_in[1];
    const int*   batch = (const int*)d_in[2];
    const float* Wrel  = (const float*)d_in[3];
    const float* brel  = (const float*)d_in[4];
    const float* Wroot = (const float*)d_in[5];
    const float* gamma = (const float*)d_in[6];
    const float* beta  = (const float*)d_in[7];
    const float* Wcls  = (const float*)d_in[8];
    const float* bcls  = (const float*)d_in[9];
    float* out = (float*)d_out;

    int N = in_sizes[0] / D;
    int E = in_sizes[1] / 2;
    int G = out_size / 10;
    int NB = (N + 1023) / 1024;
    float invN = 1.f / (float)N;
    int NTILES = (N + TILE - 1) / TILE;
    int GATHER_BLOCKS = (N * 32 + 255) / 256;
    size_t smemb = SMEM_FLOATS * sizeof(float);

    static int attr_done = 0;
    if (!attr_done) {
        cudaFuncSetAttribute(k_gemm<0>, cudaFuncAttributeMaxDynamicSharedMemorySize, (int)smemb);
        cudaFuncSetAttribute(k_gemm<1>, cudaFuncAttributeMaxDynamicSharedMemorySize, (int)smemb);
        attr_done = 1;
    }

    float *hA, *hB, *s0, *q0, *s1, *q1;
    cudaGetSymbolAddress((void**)&hA, g_hA);
    cudaGetSymbolAddress((void**)&hB, g_hB);
    cudaGetSymbolAddress((void**)&s0, g_ssum0);
    cudaGetSymbolAddress((void**)&q0, g_ssq0);
    cudaGetSymbolAddress((void**)&s1, g_ssum1);
    cudaGetSymbolAddress((void**)&q1, g_ssq1);

    // CSR build (reused by all layers)
    k_setup<<<(N + 255) / 256, 256>>>(N);
    k_hist<<<(E + 255) / 256, 256>>>(ei, E);
    k_scan1<<<NB, 256>>>(N);
    k_scan23<<<NB, 256>>>(N, NB);
    k_bucket<<<(E + 255) / 256, 256>>>(ei, E);

    // layer 0: x -> hA  (stats -> buf0)
    k_gather<0><<<GATHER_BLOCKS, 256>>>(x, nullptr, nullptr, nullptr, nullptr,
                                        nullptr, nullptr, invN, N);
    k_gemm<0><<<NTILES, 128, smemb>>>(x, hA, Wrel, brel, Wroot,
                                      nullptr, nullptr, nullptr, nullptr,
                                      s0, q0, invN, N);

    // layer 1: hA -> hB  (reads buf0 stats; stats -> buf1, zeroed at setup)
    k_gather<1><<<GATHER_BLOCKS, 256>>>(hA, s0, q0, gamma, beta,
                                        nullptr, nullptr, invN, N);
    k_gemm<1><<<NTILES, 128, smemb>>>(hA, hB, Wrel + 4096, brel + 64, Wroot + 4096,
                                      s0, q0, gamma, beta,
                                      s1, q1, invN, N);

    // layer 2: hB -> hA  (reads buf1 stats; stats -> buf0, zeroed by gather2)
    k_gather<1><<<GATHER_BLOCKS, 256>>>(hB, s1, q1, gamma + 64, beta + 64,
                                        s0, q0, invN, N);
    k_gemm<1><<<NTILES, 128, smemb>>>(hB, hA, Wrel + 8192, brel + 128, Wroot + 8192,
                                      s1, q1, gamma + 64, beta + 64,
                                      s0, q0, invN, N);

    // pool (applies layer-2 BN+ReLU from buf0 stats) + classifier
    k_pool<<<G, 256>>>(hA, batch, N, Wcls, bcls,
                       s0, q0, gamma + 128, beta + 128, invN, out);
}

// round 7
// speedup vs baseline: 2.2022x; 1.0018x over previous
#include <cuda_runtime.h>
#include <cuda_fp16.h>

#define D 64
#define MAXN 100000
#define MAXE 1250000
#define BN_EPS 1e-5f
#define TILE 128

typedef unsigned long long ull;

#define PK2(d, s)  asm("mov.b64 %0, {%1, %1};" : "=l"(d) : "f"(s))
#define FMA2(d, a, b, c) asm("fma.rn.f32x2 %0, %1, %2, %3;" : "=l"(d) : "l"(a), "l"(b), "l"(c))
#define UPK2(lo, hi, s) asm("mov.b64 {%0, %1}, %2;" : "=f"(lo), "=f"(hi) : "l"(s))

__device__ __forceinline__ __half2 u2h2(unsigned u) { return *reinterpret_cast<__half2*>(&u); }
__device__ __forceinline__ unsigned h2u(__half2 h) { return *reinterpret_cast<unsigned*>(&h); }

// ---------------- static device scratch -------------------------------------
__device__ int   g_deg[MAXN];
__device__ int   g_rowptr[MAXN + 1];
__device__ int   g_cursor[MAXN + 1];
__device__ int   g_blocksums[256];
__device__ int   g_srcsorted[MAXE];
__device__ __align__(16) __half g_xh[(size_t)MAXN * D];
__device__ __align__(16) float  g_msg[(size_t)MAXN * D];
__device__ __align__(16) __half g_hA[(size_t)MAXN * D];
__device__ __align__(16) __half g_hB[(size_t)MAXN * D];
__device__ __align__(16) float g_ssum0[D];
__device__ __align__(16) float g_ssq0[D];
__device__ __align__(16) float g_ssum1[D];
__device__ __align__(16) float g_ssq1[D];

// ---------------- setup: zero deg/stats + convert x -> fp16 ------------------
__global__ void k_setup(const float* __restrict__ x, int N, int total8) {
    int i = blockIdx.x * blockDim.x + threadIdx.x;
    if (i < N) g_deg[i] = 0;
    if (i < total8) {
        float4 a = ((const float4*)x)[i * 2];
        float4 b = ((const float4*)x)[i * 2 + 1];
        uint4 o;
        o.x = h2u(__floats2half2_rn(a.x, a.y));
        o.y = h2u(__floats2half2_rn(a.z, a.w));
        o.z = h2u(__floats2half2_rn(b.x, b.y));
        o.w = h2u(__floats2half2_rn(b.z, b.w));
        ((uint4*)g_xh)[i] = o;
    }
    if (blockIdx.x == 0 && threadIdx.x < D) {
        g_ssum0[threadIdx.x] = 0.f; g_ssq0[threadIdx.x] = 0.f;
        g_ssum1[threadIdx.x] = 0.f; g_ssq1[threadIdx.x] = 0.f;
    }
}

__global__ void k_hist(const int* __restrict__ ei, int E) {
    int e = blockIdx.x * blockDim.x + threadIdx.x;
    if (e < E) atomicAdd(&g_deg[ei[E + e]], 1);
}

__global__ void k_scan1(int N) {
    __shared__ int sh[256];
    int tid = threadIdx.x;
    int base = blockIdx.x * 1024 + tid * 4;
    int v0 = (base + 0 < N) ? g_deg[base + 0] : 0;
    int v1 = (base + 1 < N) ? g_deg[base + 1] : 0;
    int v2 = (base + 2 < N) ? g_deg[base + 2] : 0;
    int v3 = (base + 3 < N) ? g_deg[base + 3] : 0;
    int t0 = v0, t1 = t0 + v1, t2 = t1 + v2, t3 = t2 + v3;
    sh[tid] = t3;
    __syncthreads();
    for (int off = 1; off < 256; off <<= 1) {
        int add = (tid >= off) ? sh[tid - off] : 0;
        __syncthreads();
        sh[tid] += add;
        __syncthreads();
    }
    int excl = sh[tid] - t3;
    if (base + 0 < N) g_rowptr[base + 1] = excl + t0;
    if (base + 1 < N) g_rowptr[base + 2] = excl + t1;
    if (base + 2 < N) g_rowptr[base + 3] = excl + t2;
    if (base + 3 < N) g_rowptr[base + 4] = excl + t3;
    if (tid == 255) g_blocksums[blockIdx.x] = sh[255];
}

__global__ void k_scan23(int N, int NB) {
    __shared__ int sh[256];
    int tid = threadIdx.x;
    int v = (tid < NB) ? g_blocksums[tid] : 0;
    sh[tid] = v;
    __syncthreads();
    for (int off = 1; off < 256; off <<= 1) {
        int a = (tid >= off) ? sh[tid - off] : 0;
        __syncthreads();
        sh[tid] += a;
        __syncthreads();
    }
    int off = (blockIdx.x == 0) ? 0 : sh[blockIdx.x - 1];

    int base = blockIdx.x * 1024 + tid * 4;
#pragma unroll
    for (int i = 0; i < 4; i++) {
        int idx = base + i;
        if (idx < N) {
            int val = g_rowptr[idx + 1] + off;
            g_rowptr[idx + 1] = val;
            if (idx + 1 < N) g_cursor[idx + 1] = val;
        }
    }
    if (blockIdx.x == 0 && tid == 0) { g_rowptr[0] = 0; g_cursor[0] = 0; }
}

__global__ void k_bucket(const int* __restrict__ ei, int E) {
    int e = blockIdx.x * blockDim.x + threadIdx.x;
    if (e < E) {
        int d = ei[E + e];
        int pos = atomicAdd(&g_cursor[d], 1);
        g_srcsorted[pos] = ei[e];
    }
}

// ---------------- gather: warp per node, fp16 rows, 4-neighbor split ---------
template<int TF>
__global__ void __launch_bounds__(256) k_gather(
    const __half* __restrict__ x_src,
    const float* __restrict__ ssum, const float* __restrict__ ssq,
    const float* __restrict__ gamma_p, const float* __restrict__ beta_p,
    float* zsum, float* zsq, float invN, int N)
{
    if (TF && zsum != nullptr && blockIdx.x == 0 && threadIdx.x < D) {
        zsum[threadIdx.x] = 0.f;
        zsq[threadIdx.x]  = 0.f;
    }

    int lane = threadIdx.x & 31;
    int node = (blockIdx.x * blockDim.x + threadIdx.x) >> 5;
    if (node >= N) return;
    int q = lane >> 3;      // neighbor sub-slot 0..3
    int c8 = lane & 7;      // column group of 8 halves

    __half2 sc2[4], sh2[4];
    if (TF) {
#pragma unroll
        for (int j = 0; j < 4; j++) {
            float scf[2], shf[2];
#pragma unroll
            for (int c = 0; c < 2; c++) {
                int col = c8 * 8 + j * 2 + c;
                float mean = ssum[col] * invN;
                float var = fmaf(-mean, mean, ssq[col] * invN);
                var = var < 0.f ? 0.f : var;
                float s = gamma_p[col] * rsqrtf(var + BN_EPS);
                scf[c] = s;
                shf[c] = beta_p[col] - mean * s;
            }
            sc2[j] = __floats2half2_rn(scf[0], scf[1]);
            sh2[j] = __floats2half2_rn(shf[0], shf[1]);
        }
    }

    float acc[8];
#pragma unroll
    for (int j = 0; j < 8; j++) acc[j] = 0.f;

    int rs = g_rowptr[node], re = g_rowptr[node + 1];
    for (int base = rs; base < re; base += 32) {
        int jj = base + lane;
        int sj = (jj < re) ? g_srcsorted[jj] : 0;
        int cnt = min(32, re - base);
        for (int u = 0; u < cnt; u += 4) {
            int i0 = u + q;
            int s = __shfl_sync(0xffffffffu, sj, i0 & 31);
            if (i0 < cnt) {
                uint4 raw = *(const uint4*)(x_src + (size_t)s * D + c8 * 8);
                __half2 v0 = u2h2(raw.x), v1 = u2h2(raw.y), v2 = u2h2(raw.z), v3 = u2h2(raw.w);
                if (TF) {
                    __half2 z = __float2half2_rn(0.f);
                    v0 = __hmax2(__hfma2(v0, sc2[0], sh2[0]), z);
                    v1 = __hmax2(__hfma2(v1, sc2[1], sh2[1]), z);
                    v2 = __hmax2(__hfma2(v2, sc2[2], sh2[2]), z);
                    v3 = __hmax2(__hfma2(v3, sc2[3], sh2[3]), z);
                }
                float2 f0 = __half22float2(v0), f1 = __half22float2(v1);
                float2 f2 = __half22float2(v2), f3 = __half22float2(v3);
                acc[0] += f0.x; acc[1] += f0.y; acc[2] += f1.x; acc[3] += f1.y;
                acc[4] += f2.x; acc[5] += f2.y; acc[6] += f3.x; acc[7] += f3.y;
            }
        }
    }

#pragma unroll
    for (int off = 8; off <= 16; off <<= 1)
#pragma unroll
        for (int j = 0; j < 8; j++) acc[j] += __shfl_xor_sync(0xffffffffu, acc[j], off);

    if (lane < 8) {
        float4* o = (float4*)(g_msg + (size_t)node * D + lane * 8);
        o[0] = make_float4(acc[0], acc[1], acc[2], acc[3]);
        o[1] = make_float4(acc[4], acc[5], acc[6], acc[7]);
    }
}

// ---------------- block-tiled dual GEMM + BN stats ---------------------------
// 128 nodes/block, 128 threads, 4 strided rows/thread {p, p+32, p+64, p+96}.
#define WROW 68
#define AROW 68
#define OFF_WB  (64 * WROW)
#define OFF_M   (2 * 64 * WROW)
#define OFF_X   (OFF_M + TILE * AROW)
#define OFF_BR  (OFF_X + TILE * AROW)
#define OFF_SC  (OFF_BR + 64)
#define OFF_SH  (OFF_SC + 64)
#define OFF_SUM (OFF_SH + 64)
#define OFF_SQ  (OFF_SUM + 64)
#define SMEM_FLOATS (OFF_SQ + 64)

__device__ __forceinline__ void bnrelu4(float4& a, const float4& sc, const float4& sh) {
    a.x = fmaxf(fmaf(a.x, sc.x, sh.x), 0.f);
    a.y = fmaxf(fmaf(a.y, sc.y, sh.y), 0.f);
    a.z = fmaxf(fmaf(a.z, sc.z, sh.z), 0.f);
    a.w = fmaxf(fmaf(a.w, sc.w, sh.w), 0.f);
}

template<int TF>
__global__ void __launch_bounds__(128) k_gemm(
    const __half* __restrict__ x_src, __half* __restrict__ h_out,
    const float* __restrict__ Wrel, const float* __restrict__ brel,
    const float* __restrict__ Wroot,
    const float* __restrict__ ssum_in, const float* __restrict__ ssq_in,
    const float* __restrict__ gamma_p, const float* __restrict__ beta_p,
    float* __restrict__ ssum_out, float* __restrict__ ssq_out,
    float invN, int N)
{
    extern __shared__ float smem[];
    float* wa_sh = smem;
    float* wb_sh = smem + OFF_WB;
    float* m_sh  = smem + OFF_M;
    float* x_sh  = smem + OFF_X;
    float* s_br  = smem + OFF_BR;
    float* s_sc  = smem + OFF_SC;
    float* s_shf = smem + OFF_SH;
    float* s_sum = smem + OFF_SUM;
    float* s_sq  = smem + OFF_SQ;

    int tid = threadIdx.x;
    int tile0 = blockIdx.x * TILE;

    // stage weights with 2-group padding
    for (int i = tid; i < 1024; i += 128) {
        int k = i >> 4, cq = i & 15;
        int dst = k * 17 + cq + (cq >= 8 ? 1 : 0);
        ((float4*)wa_sh)[dst] = ((const float4*)Wrel)[i];
        ((float4*)wb_sh)[dst] = ((const float4*)Wroot)[i];
    }
    if (tid < 64) {
        s_br[tid] = brel[tid];
        s_sum[tid] = 0.f;
        if (TF) {
            float mean = ssum_in[tid] * invN;
            float var = fmaf(-mean, mean, ssq_in[tid] * invN);
            var = var < 0.f ? 0.f : var;
            float s = gamma_p[tid] * rsqrtf(var + BN_EPS);
            s_sc[tid] = s;
            s_shf[tid] = beta_p[tid] - mean * s;
        }
    } else {
        s_sq[tid - 64] = 0.f;
    }
    __syncthreads();

    // stage msg (fp32)
    for (int i = tid; i < TILE * 16; i += 128) {
        int r = i >> 4, c4 = i & 15;
        int node = tile0 + r;
        float4 mval = make_float4(0.f, 0.f, 0.f, 0.f);
        if (node < N) mval = ((const float4*)(g_msg + (size_t)node * D))[c4];
        ((float4*)(m_sh + r * AROW))[c4] = mval;
    }
    // stage x (fp16 -> fp32, BN+ReLU if TF)
    for (int i = tid; i < TILE * 8; i += 128) {
        int r = i >> 3, c8 = i & 7;
        int node = tile0 + r;
        float4 lo = make_float4(0.f, 0.f, 0.f, 0.f), hi = lo;
        if (node < N) {
            uint4 raw = ((const uint4*)(x_src + (size_t)node * D))[c8];
            float2 f0 = __half22float2(u2h2(raw.x));
            float2 f1 = __half22float2(u2h2(raw.y));
            float2 f2 = __half22float2(u2h2(raw.z));
            float2 f3 = __half22float2(u2h2(raw.w));
            lo = make_float4(f0.x, f0.y, f1.x, f1.y);
            hi = make_float4(f2.x, f2.y, f3.x, f3.y);
            if (TF) {
                float4 sa = ((float4*)s_sc)[c8 * 2], ha = ((float4*)s_shf)[c8 * 2];
                float4 sb = ((float4*)s_sc)[c8 * 2 + 1], hb = ((float4*)s_shf)[c8 * 2 + 1];
                bnrelu4(lo, sa, ha);
                bnrelu4(hi, sb, hb);
            }
        }
        *(float4*)(x_sh + r * AROW + c8 * 8) = lo;
        *(float4*)(x_sh + r * AROW + c8 * 8 + 4) = hi;
    }
    __syncthreads();

    int lane = tid & 31;
    int cg = tid & 3;
    int p = tid >> 2;               // 0..31; rows p, p+32, p+64, p+96
    int c0 = cg * 16;
    int c0f = c0 + (cg >> 1) * 4;

    ull acc[4][8];
    {
        const ull* br2 = (const ull*)(s_br + c0);
#pragma unroll
        for (int qq = 0; qq < 8; qq++) {
            ull b = br2[qq];
            acc[0][qq] = b; acc[1][qq] = b; acc[2][qq] = b; acc[3][qq] = b;
        }
    }

#pragma unroll 2
    for (int kk = 0; kk < 16; kk++) {
        float4 mq[4], xq[4];
#pragma unroll
        for (int j = 0; j < 4; j++) {
            mq[j] = *(const float4*)(m_sh + (p + 32 * j) * AROW + kk * 4);
            xq[j] = *(const float4*)(x_sh + (p + 32 * j) * AROW + kk * 4);
        }
#pragma unroll
        for (int dk = 0; dk < 4; dk++) {
            int k = kk * 4 + dk;
            const ulonglong2* wa2 = (const ulonglong2*)(wa_sh + k * WROW + c0f);
            const ulonglong2* wb2 = (const ulonglong2*)(wb_sh + k * WROW + c0f);
            ulonglong2 A0 = wa2[0], A1 = wa2[1], A2 = wa2[2], A3 = wa2[3];
            ulonglong2 B0 = wb2[0], B1 = wb2[1], B2 = wb2[2], B3 = wb2[3];
#pragma unroll
            for (int j = 0; j < 4; j++) {
                ull mm, xx;
                PK2(mm, ((const float*)&mq[j])[dk]);
                PK2(xx, ((const float*)&xq[j])[dk]);
                FMA2(acc[j][0], mm, A0.x, acc[j][0]); FMA2(acc[j][1], mm, A0.y, acc[j][1]);
                FMA2(acc[j][2], mm, A1.x, acc[j][2]); FMA2(acc[j][3], mm, A1.y, acc[j][3]);
                FMA2(acc[j][4], mm, A2.x, acc[j][4]); FMA2(acc[j][5], mm, A2.y, acc[j][5]);
                FMA2(acc[j][6], mm, A3.x, acc[j][6]); FMA2(acc[j][7], mm, A3.y, acc[j][7]);
                FMA2(acc[j][0], xx, B0.x, acc[j][0]); FMA2(acc[j][1], xx, B0.y, acc[j][1]);
                FMA2(acc[j][2], xx, B1.x, acc[j][2]); FMA2(acc[j][3], xx, B1.y, acc[j][3]);
                FMA2(acc[j][4], xx, B2.x, acc[j][4]); FMA2(acc[j][5], xx, B2.y, acc[j][5]);
                FMA2(acc[j][6], xx, B3.x, acc[j][6]); FMA2(acc[j][7], xx, B3.y, acc[j][7]);
            }
        }
    }

    float s[16], q2[16];
#pragma unroll
    for (int qq = 0; qq < 16; qq++) { s[qq] = 0.f; q2[qq] = 0.f; }

#pragma unroll
    for (int j = 0; j < 4; j++) {
        int node = tile0 + p + 32 * j;
        bool valid = node < N;
        float h[16];
#pragma unroll
        for (int qq = 0; qq < 8; qq++) UPK2(h[2 * qq], h[2 * qq + 1], acc[j][qq]);
        if (!valid) {
#pragma unroll
            for (int qq = 0; qq < 16; qq++) h[qq] = 0.f;
        }
#pragma unroll
        for (int qq = 0; qq < 16; qq++) { s[qq] += h[qq]; q2[qq] = fmaf(h[qq], h[qq], q2[qq]); }
        if (valid) {
            uint4 o0, o1;
            o0.x = h2u(__floats2half2_rn(h[0], h[1]));
            o0.y = h2u(__floats2half2_rn(h[2], h[3]));
            o0.z = h2u(__floats2half2_rn(h[4], h[5]));
            o0.w = h2u(__floats2half2_rn(h[6], h[7]));
            o1.x = h2u(__floats2half2_rn(h[8], h[9]));
            o1.y = h2u(__floats2half2_rn(h[10], h[11]));
            o1.z = h2u(__floats2half2_rn(h[12], h[13]));
            o1.w = h2u(__floats2half2_rn(h[14], h[15]));
            uint4* op = (uint4*)(h_out + (size_t)node * D + c0);
            op[0] = o0;
            op[1] = o1;
        }
    }

#pragma unroll
    for (int off = 4; off <= 16; off <<= 1) {
#pragma unroll
        for (int qq = 0; qq < 16; qq++) {
            s[qq]  += __shfl_xor_sync(0xffffffffu, s[qq], off);
            q2[qq] += __shfl_xor_sync(0xffffffffu, q2[qq], off);
        }
    }
    if (lane < 4) {
        int cc = lane * 16;
#pragma unroll
        for (int qq = 0; qq < 16; qq++) {
            atomicAdd(&s_sum[cc + qq], s[qq]);
            atomicAdd(&s_sq[cc + qq], q2[qq]);
        }
    }

    __syncthreads();
    if (tid < 64) atomicAdd(&ssum_out[tid], s_sum[tid]);
    else atomicAdd(&ssq_out[tid - 64], s_sq[tid - 64]);
}

// ---------------- pooling + classifier (final BN+ReLU inline) ----------------
__global__ void __launch_bounds__(1024) k_pool(
    const __half* __restrict__ hfin, const int* __restrict__ batch, int N,
    const float* __restrict__ Wcls, const float* __restrict__ bcls,
    const float* __restrict__ ssum, const float* __restrict__ ssq,
    const float* __restrict__ gamma_p, const float* __restrict__ beta_p,
    float invN, float* __restrict__ out)
{
    __shared__ float s_pool[D];
    int g = blockIdx.x, tid = threadIdx.x;

    int lo = 0, hi = N;
    while (lo < hi) { int mid = (lo + hi) >> 1; if (batch[mid] < g) lo = mid + 1; else hi = mid; }
    int start = lo;
    hi = N;
    while (lo < hi) { int mid = (lo + hi) >> 1; if (batch[mid] < g + 1) lo = mid + 1; else hi = mid; }
    int end = lo;

    if (tid < D) s_pool[tid] = 0.f;
    __syncthreads();

    int col = tid & 63, rg = tid >> 6;   // 16 row-groups
    float mean = ssum[col] * invN;
    float var = fmaf(-mean, mean, ssq[col] * invN);
    var = var < 0.f ? 0.f : var;
    float sc = gamma_p[col] * rsqrtf(var + BN_EPS);
    float sh_ = beta_p[col] - mean * sc;

    float p0 = 0.f, p1 = 0.f, p2 = 0.f, p3 = 0.f;
    int r = start + rg;
    for (; r + 48 < end; r += 64) {
        float a0 = __half2float(hfin[(size_t)(r     ) * D + col]);
        float a1 = __half2float(hfin[(size_t)(r + 16) * D + col]);
        float a2 = __half2float(hfin[(size_t)(r + 32) * D + col]);
        float a3 = __half2float(hfin[(size_t)(r + 48) * D + col]);
        p0 += fmaxf(fmaf(a0, sc, sh_), 0.f);
        p1 += fmaxf(fmaf(a1, sc, sh_), 0.f);
        p2 += fmaxf(fmaf(a2, sc, sh_), 0.f);
        p3 += fmaxf(fmaf(a3, sc, sh_), 0.f);
    }
    for (; r < end; r += 16)
        p0 += fmaxf(fmaf(__half2float(hfin[(size_t)r * D + col]), sc, sh_), 0.f);
    atomicAdd(&s_pool[col], ((p0 + p1) + (p2 + p3)));
    __syncthreads();

    float cnt = (float)(end - start);
    float denom = cnt > 1.f ? cnt : 1.f;
    if (tid < D) s_pool[tid] /= denom;
    __syncthreads();

    if (tid < 10) {
        float acc = bcls[tid];
#pragma unroll
        for (int d = 0; d < D; d++) acc = fmaf(s_pool[d], Wcls[d * 10 + tid], acc);
        out[g * 10 + tid] = acc;
    }
}

// ---------------- launch -----------------------------------------------------
extern "C" void kernel_launch(void* const* d_in, const int* in_sizes, int n_in,
                              void* d_out, int out_size)
{
    const float* x     = (const float*)d_in[0];
    const int*   ei    = (const int*)d_in[1];
    const int*   batch = (const int*)d_in[2];
    const float* Wrel  = (const float*)d_in[3];
    const float* brel  = (const float*)d_in[4];
    const float* Wroot = (const float*)d_in[5];
    const float* gamma = (const float*)d_in[6];
    const float* beta  = (const float*)d_in[7];
    const float* Wcls  = (const float*)d_in[8];
    const float* bcls  = (const float*)d_in[9];
    float* out = (float*)d_out;

    int N = in_sizes[0] / D;
    int E = in_sizes[1] / 2;
    int G = out_size / 10;
    int NB = (N + 1023) / 1024;
    float invN = 1.f / (float)N;
    int NTILES = (N + TILE - 1) / TILE;
    int GATHER_BLOCKS = (N * 32 + 255) / 256;
    int total8 = N * 8;
    size_t smemb = SMEM_FLOATS * sizeof(float);

    static int attr_done = 0;
    if (!attr_done) {
        cudaFuncSetAttribute(k_gemm<0>, cudaFuncAttributeMaxDynamicSharedMemorySize, (int)smemb);
        cudaFuncSetAttribute(k_gemm<1>, cudaFuncAttributeMaxDynamicSharedMemorySize, (int)smemb);
        attr_done = 1;
    }

    __half *xh, *hA, *hB;
    float *s0, *q0, *s1, *q1;
    cudaGetSymbolAddress((void**)&xh, g_xh);
    cudaGetSymbolAddress((void**)&hA, g_hA);
    cudaGetSymbolAddress((void**)&hB, g_hB);
    cudaGetSymbolAddress((void**)&s0, g_ssum0);
    cudaGetSymbolAddress((void**)&q0, g_ssq0);
    cudaGetSymbolAddress((void**)&s1, g_ssum1);
    cudaGetSymbolAddress((void**)&q1, g_ssq1);

    // CSR build + fp16 convert
    k_setup<<<(total8 + 255) / 256, 256>>>(x, N, total8);
    k_hist<<<(E + 255) / 256, 256>>>(ei, E);
    k_scan1<<<NB, 256>>>(N);
    k_scan23<<<NB, 256>>>(N, NB);
    k_bucket<<<(E + 255) / 256, 256>>>(ei, E);

    // layer 0: xh -> hA (stats -> buf0)
    k_gather<0><<<GATHER_BLOCKS, 256>>>(xh, nullptr, nullptr, nullptr, nullptr,
                                        nullptr, nullptr, invN, N);
    k_gemm<0><<<NTILES, 128, smemb>>>(xh, hA, Wrel, brel, Wroot,
                                      nullptr, nullptr, nullptr, nullptr,
                                      s0, q0, invN, N);

    // layer 1: hA -> hB (BN from buf0; stats -> buf1)
    k_gather<1><<<GATHER_BLOCKS, 256>>>(hA, s0, q0, gamma, beta,
                                        nullptr, nullptr, invN, N);
    k_gemm<1><<<NTILES, 128, smemb>>>(hA, hB, Wrel + 4096, brel + 64, Wroot + 4096,
                                      s0, q0, gamma, beta,
                                      s1, q1, invN, N);

    // layer 2: hB -> hA (BN from buf1; stats -> buf0, zeroed by gather2 block 0)
    k_gather<1><<<GATHER_BLOCKS, 256>>>(hB, s1, q1, gamma + 64, beta + 64,
                                        s0, q0, invN, N);
    k_gemm<1><<<NTILES, 128, smemb>>>(hB, hA, Wrel + 8192, brel + 128, Wroot + 8192,
                                      s1, q1, gamma + 64, beta + 64,
                                      s0, q0, invN, N);

    // pool (applies layer-2 BN+ReLU from buf0 stats) + classifier
    k_pool<<<G, 1024>>>(hA, batch, N, Wcls, bcls,
                        s0, q0, gamma + 128, beta + 128, invN, out);
}